// round 11
// baseline (speedup 1.0000x reference)
#include <cuda_runtime.h>
#include <cuda_bf16.h>
#include <cstdint>

// EfficientReynoldsFeatureOperator:
//   x:  (B=8, N=8192, D=512) fp32
//   W:  (512, 128) fp32, pw: (128) fp32
//   out:(B, N, R) fp32,  out[b,n,r] = (mean_n(x[b]) @ W)[r] * pw[r]
// Using mean_n(x @ W) == (mean_n x) @ W.
//
// Structure (3 launches, best-of-session recombination):
//   k1: CHUNKS=256 -> 2048 blocks, 32 rows each (5.75 TB/s proven config)
//   k2: single merged reduction+projection (8 blocks, 512 thr)
//   k3: 8-way ILP STG broadcast (store-path wall ~3.7 TB/s, closed)

#define B_DIM 8
#define N_DIM 8192
#define D_DIM 512
#define R_DIM 128
#define CHUNKS 256                           // chunks per batch
#define ROWS_PER_CHUNK (N_DIM / CHUNKS)      // 32

__device__ float g_partial[B_DIM * CHUNKS * D_DIM];   // 4 MB scratch (L2-hot)
__device__ float g_y[B_DIM * R_DIM];                  // 4 KB

// ---------------------------------------------------------------------------
// K1: partial column sums of x over n. (round-3/4 proven 5.75 TB/s body)
// grid = (CHUNKS, B) = 2048 blocks, 128 threads; thread t owns float4 slot t.
// 8 back-to-back LDG.128 per step (MLP_p1=8), 2 accumulators, __ldcs.
// ---------------------------------------------------------------------------
__global__ __launch_bounds__(128, 8) void k1_colsum_partial(const float* __restrict__ x) {
    const int chunk = blockIdx.x;
    const int b     = blockIdx.y;
    const int t     = threadIdx.x;            // 0..127

    const float4* xrow = reinterpret_cast<const float4*>(
        x + ((size_t)b * N_DIM + (size_t)chunk * ROWS_PER_CHUNK) * D_DIM);

    float4 a0 = make_float4(0.f, 0.f, 0.f, 0.f);
    float4 a1 = make_float4(0.f, 0.f, 0.f, 0.f);

#pragma unroll
    for (int i = 0; i < ROWS_PER_CHUNK; i += 8) {
        float4 v0 = __ldcs(&xrow[(size_t)(i + 0) * 128 + t]);
        float4 v1 = __ldcs(&xrow[(size_t)(i + 1) * 128 + t]);
        float4 v2 = __ldcs(&xrow[(size_t)(i + 2) * 128 + t]);
        float4 v3 = __ldcs(&xrow[(size_t)(i + 3) * 128 + t]);
        float4 v4 = __ldcs(&xrow[(size_t)(i + 4) * 128 + t]);
        float4 v5 = __ldcs(&xrow[(size_t)(i + 5) * 128 + t]);
        float4 v6 = __ldcs(&xrow[(size_t)(i + 6) * 128 + t]);
        float4 v7 = __ldcs(&xrow[(size_t)(i + 7) * 128 + t]);
        a0.x += v0.x; a0.y += v0.y; a0.z += v0.z; a0.w += v0.w;
        a1.x += v1.x; a1.y += v1.y; a1.z += v1.z; a1.w += v1.w;
        a0.x += v2.x; a0.y += v2.y; a0.z += v2.z; a0.w += v2.w;
        a1.x += v3.x; a1.y += v3.y; a1.z += v3.z; a1.w += v3.w;
        a0.x += v4.x; a0.y += v4.y; a0.z += v4.z; a0.w += v4.w;
        a1.x += v5.x; a1.y += v5.y; a1.z += v5.z; a1.w += v5.w;
        a0.x += v6.x; a0.y += v6.y; a0.z += v6.z; a0.w += v6.w;
        a1.x += v7.x; a1.y += v7.y; a1.z += v7.z; a1.w += v7.w;
    }
    a0.x += a1.x; a0.y += a1.y; a0.z += a1.z; a0.w += a1.w;

    float4* p = reinterpret_cast<float4*>(
        g_partial + ((size_t)b * CHUNKS + chunk) * D_DIM);
    p[t] = a0;
}

// ---------------------------------------------------------------------------
// K2 (merged): per batch, reduce 256 chunk-partials, project, scale.
// grid = B, 512 threads.
//   Phase 1: group g = t>>7 (4 groups), d4 = t&127. Group g sums 64 chunks
//            [64g, 64g+64) -- float4, fully coalesced, L2-hot, ILP 2.
//   Phase 2: smem combine 4 groups -> s_mean.
//   Phase 3: warp w owns d-slice [32w,32w+32); lanes own r (coalesced W).
//   Phase 4: smem reduce 16 warp partials per r, scale by pw.
// ---------------------------------------------------------------------------
__global__ __launch_bounds__(512) void k2_finish_and_project(
    const float* __restrict__ W, const float* __restrict__ pw) {
    __shared__ float s_part[4][D_DIM];
    __shared__ float s_mean[D_DIM];
    __shared__ float s_red[16][R_DIM];
    const int b = blockIdx.x;
    const int t = threadIdx.x;
    const int g  = t >> 7;        // 0..3
    const int d4 = t & 127;       // 0..127

    const float4* pbase = reinterpret_cast<const float4*>(
        g_partial + (size_t)b * CHUNKS * D_DIM);

    float4 acc0 = make_float4(0.f, 0.f, 0.f, 0.f);
    float4 acc1 = make_float4(0.f, 0.f, 0.f, 0.f);
#pragma unroll 8
    for (int c = g * 64; c < g * 64 + 64; c += 2) {
        float4 v0 = __ldcg(&pbase[(size_t)c * 128 + d4]);
        float4 v1 = __ldcg(&pbase[(size_t)(c + 1) * 128 + d4]);
        acc0.x += v0.x; acc0.y += v0.y; acc0.z += v0.z; acc0.w += v0.w;
        acc1.x += v1.x; acc1.y += v1.y; acc1.z += v1.z; acc1.w += v1.w;
    }
    acc0.x += acc1.x; acc0.y += acc1.y; acc0.z += acc1.z; acc0.w += acc1.w;
    s_part[g][4 * d4 + 0] = acc0.x;
    s_part[g][4 * d4 + 1] = acc0.y;
    s_part[g][4 * d4 + 2] = acc0.z;
    s_part[g][4 * d4 + 3] = acc0.w;
    __syncthreads();

    s_mean[t] = (s_part[0][t] + s_part[1][t] + s_part[2][t] + s_part[3][t])
                * (1.0f / (float)N_DIM);
    __syncthreads();

    const int w    = t >> 5;
    const int lane = t & 31;
    float p0 = 0.f, p1 = 0.f, p2 = 0.f, p3 = 0.f;
#pragma unroll
    for (int i = 0; i < 32; ++i) {
        const int d = w * 32 + i;
        const float m = s_mean[d];
        const float* Wr = W + (size_t)d * R_DIM;
        p0 = fmaf(m, __ldg(&Wr[lane]),      p0);
        p1 = fmaf(m, __ldg(&Wr[32 + lane]), p1);
        p2 = fmaf(m, __ldg(&Wr[64 + lane]), p2);
        p3 = fmaf(m, __ldg(&Wr[96 + lane]), p3);
    }
    s_red[w][lane]      = p0;
    s_red[w][32 + lane] = p1;
    s_red[w][64 + lane] = p2;
    s_red[w][96 + lane] = p3;
    __syncthreads();

    if (t < R_DIM) {
        float y = 0.f;
#pragma unroll
        for (int k = 0; k < 16; ++k)
            y += s_red[k][t];
        g_y[b * R_DIM + t] = y * pw[t];
    }
}

// ---------------------------------------------------------------------------
// K3: broadcast y over the sequence axis. (round-5 proven: 8 STG.128 ILP)
// ---------------------------------------------------------------------------
__global__ __launch_bounds__(256) void k3_broadcast(float4* __restrict__ out) {
    const int tid = blockIdx.x * blockDim.x + threadIdx.x;  // 0..262143
    const int r4  = tid & (R_DIM / 4 - 1);
    const float4* y4 = reinterpret_cast<const float4*>(g_y);
#pragma unroll
    for (int b = 0; b < B_DIM; ++b) {
        float4 v = __ldg(&y4[b * (R_DIM / 4) + r4]);
        out[(size_t)b * (N_DIM * R_DIM / 4) + tid] = v;
    }
}

// ---------------------------------------------------------------------------
extern "C" void kernel_launch(void* const* d_in, const int* in_sizes, int n_in,
                              void* d_out, int out_size) {
    const float* x  = (const float*)d_in[0];
    const float* W  = (const float*)d_in[1];
    const float* pw = (const float*)d_in[2];
    float* out      = (float*)d_out;

    (void)in_sizes; (void)n_in; (void)out_size;

    dim3 g1(CHUNKS, B_DIM);                    // 2048 blocks
    k1_colsum_partial<<<g1, 128>>>(x);

    k2_finish_and_project<<<B_DIM, 512>>>(W, pw);

    const int perBatch4 = N_DIM * R_DIM / 4;   // 262144
    k3_broadcast<<<perBatch4 / 256, 256>>>((float4*)out);
}

// round 12
// speedup vs baseline: 1.0674x; 1.0674x over previous
#include <cuda_runtime.h>
#include <cuda_bf16.h>
#include <cstdint>

// EfficientReynoldsFeatureOperator:
//   x:  (B=8, N=8192, D=512) fp32
//   W:  (512, 128) fp32, pw: (128) fp32
//   out:(B, N, R) fp32,  out[b,n,r] = (mean_n(x[b]) @ W)[r] * pw[r]
// Using mean_n(x @ W) == (mean_n x) @ W.
//
// 3 launches, every stage >=256 blocks (round 11 re-proved 8-block stages
// cost ~9us pulling L2):
//   k1:     2048 blocks, proven 5.8 TB/s MLP-8 __ldcs reduction -> 4MB partials
//   k2proj: 256 blocks, d-sliced reduce+project -> 32 partial y's per batch
//   k3sum:  1024 blocks, sum 32 partials (hides under stores) + broadcast

#define B_DIM 8
#define N_DIM 8192
#define D_DIM 512
#define R_DIM 128
#define CHUNKS 256                           // chunks per batch
#define ROWS_PER_CHUNK (N_DIM / CHUNKS)      // 32
#define NJ 32                                // d-slices
#define SLICE_D (D_DIM / NJ)                 // 16

__device__ float g_partial[B_DIM * CHUNKS * D_DIM];   // 4 MB scratch (L2-hot)
__device__ float g_yp[B_DIM * NJ * R_DIM];            // 128 KB partial y's

// ---------------------------------------------------------------------------
// K1: partial column sums of x over n. (proven 5.8 TB/s body, unchanged)
// grid = (CHUNKS, B) = 2048 blocks, 128 threads; thread t owns float4 slot t.
// ---------------------------------------------------------------------------
__global__ __launch_bounds__(128, 8) void k1_colsum_partial(const float* __restrict__ x) {
    const int chunk = blockIdx.x;
    const int b     = blockIdx.y;
    const int t     = threadIdx.x;            // 0..127

    const float4* xrow = reinterpret_cast<const float4*>(
        x + ((size_t)b * N_DIM + (size_t)chunk * ROWS_PER_CHUNK) * D_DIM);

    float4 a0 = make_float4(0.f, 0.f, 0.f, 0.f);
    float4 a1 = make_float4(0.f, 0.f, 0.f, 0.f);

#pragma unroll
    for (int i = 0; i < ROWS_PER_CHUNK; i += 8) {
        float4 v0 = __ldcs(&xrow[(size_t)(i + 0) * 128 + t]);
        float4 v1 = __ldcs(&xrow[(size_t)(i + 1) * 128 + t]);
        float4 v2 = __ldcs(&xrow[(size_t)(i + 2) * 128 + t]);
        float4 v3 = __ldcs(&xrow[(size_t)(i + 3) * 128 + t]);
        float4 v4 = __ldcs(&xrow[(size_t)(i + 4) * 128 + t]);
        float4 v5 = __ldcs(&xrow[(size_t)(i + 5) * 128 + t]);
        float4 v6 = __ldcs(&xrow[(size_t)(i + 6) * 128 + t]);
        float4 v7 = __ldcs(&xrow[(size_t)(i + 7) * 128 + t]);
        a0.x += v0.x; a0.y += v0.y; a0.z += v0.z; a0.w += v0.w;
        a1.x += v1.x; a1.y += v1.y; a1.z += v1.z; a1.w += v1.w;
        a0.x += v2.x; a0.y += v2.y; a0.z += v2.z; a0.w += v2.w;
        a1.x += v3.x; a1.y += v3.y; a1.z += v3.z; a1.w += v3.w;
        a0.x += v4.x; a0.y += v4.y; a0.z += v4.z; a0.w += v4.w;
        a1.x += v5.x; a1.y += v5.y; a1.z += v5.z; a1.w += v5.w;
        a0.x += v6.x; a0.y += v6.y; a0.z += v6.z; a0.w += v6.w;
        a1.x += v7.x; a1.y += v7.y; a1.z += v7.z; a1.w += v7.w;
    }
    a0.x += a1.x; a0.y += a1.y; a0.z += a1.z; a0.w += a1.w;

    float4* p = reinterpret_cast<float4*>(
        g_partial + ((size_t)b * CHUNKS + chunk) * D_DIM);
    p[t] = a0;
}

// ---------------------------------------------------------------------------
// K2proj: d-sliced reduce + project. grid = (NJ, B) = 256 blocks, 128 thr.
// Block (j,b): d-slice [16j, 16j+16).
//   Phase 1: q = t&3 (float4 within slice), lane = t>>2 (chunk lane).
//            Thread sums chunks lane, lane+32, ..., (8 loads, coalesced
//            within warp across q/lane). Tree-reduce 32 lanes in smem.
//   Phase 2: thread t = r. acc = sum_dd s_mean[dd]*W[(16j+dd)*128+r];
//            g_yp[b][j][r] = acc * pw[r]. (1/N folded into s_mean.)
// ---------------------------------------------------------------------------
__global__ __launch_bounds__(128) void k2proj(const float* __restrict__ W,
                                              const float* __restrict__ pw) {
    __shared__ float4 red[128];
    __shared__ float  s_mean[SLICE_D];
    const int j = blockIdx.x;
    const int b = blockIdx.y;
    const int t = threadIdx.x;
    const int q    = t & 3;           // float4 within 16-d slice
    const int lane = t >> 2;          // 0..31 chunk lane

    const float4* p4 = reinterpret_cast<const float4*>(g_partial)
                     + (size_t)b * CHUNKS * 128;

    float4 acc = make_float4(0.f, 0.f, 0.f, 0.f);
#pragma unroll
    for (int k = 0; k < 8; ++k) {
        const int c = lane + 32 * k;
        float4 v = __ldcg(&p4[(size_t)c * 128 + j * 4 + q]);
        acc.x += v.x; acc.y += v.y; acc.z += v.z; acc.w += v.w;
    }
    red[t] = acc;
    __syncthreads();

#pragma unroll
    for (int off = 16; off >= 1; off >>= 1) {
        if (lane < off) {
            float4 o = red[q + 4 * (lane + off)];
            float4 m = red[q + 4 * lane];
            m.x += o.x; m.y += o.y; m.z += o.z; m.w += o.w;
            red[q + 4 * lane] = m;
        }
        __syncthreads();
    }
    if (t < 4) {
        const float invN = 1.0f / (float)N_DIM;
        float4 m = red[t];
        s_mean[4 * t + 0] = m.x * invN;
        s_mean[4 * t + 1] = m.y * invN;
        s_mean[4 * t + 2] = m.z * invN;
        s_mean[4 * t + 3] = m.w * invN;
    }
    __syncthreads();

    float acc_r = 0.f;
#pragma unroll
    for (int dd = 0; dd < SLICE_D; ++dd)
        acc_r = fmaf(s_mean[dd], __ldg(&W[(size_t)(j * SLICE_D + dd) * R_DIM + t]), acc_r);

    g_yp[((size_t)b * NJ + j) * R_DIM + t] = acc_r * __ldg(&pw[t]);
}

// ---------------------------------------------------------------------------
// K3sum: sum the 32 partial y's, then broadcast. grid = 1024 blocks, 256 thr.
// Block blk: batch b = blk>>7, 32KB segment seg = blk&127.
// Prefix: 32 coalesced float4 loads/thread from hot 128KB g_yp (hides under
// store latency). Then 8 independent STG.128 per thread (proven pattern).
// ---------------------------------------------------------------------------
__global__ __launch_bounds__(256) void k3sum_broadcast(float4* __restrict__ out4) {
    const int blk = blockIdx.x;
    const int b   = blk >> 7;
    const int seg = blk & 127;
    const int t   = threadIdx.x;
    const int c4  = t & 31;

    const float4* yp4 = reinterpret_cast<const float4*>(g_yp)
                      + (size_t)b * NJ * (R_DIM / 4);

    float4 s0 = make_float4(0.f, 0.f, 0.f, 0.f);
    float4 s1 = make_float4(0.f, 0.f, 0.f, 0.f);
    float4 s2 = make_float4(0.f, 0.f, 0.f, 0.f);
    float4 s3 = make_float4(0.f, 0.f, 0.f, 0.f);
#pragma unroll
    for (int jj = 0; jj < NJ; jj += 4) {
        float4 u0 = __ldg(&yp4[(size_t)(jj + 0) * 32 + c4]);
        float4 u1 = __ldg(&yp4[(size_t)(jj + 1) * 32 + c4]);
        float4 u2 = __ldg(&yp4[(size_t)(jj + 2) * 32 + c4]);
        float4 u3 = __ldg(&yp4[(size_t)(jj + 3) * 32 + c4]);
        s0.x += u0.x; s0.y += u0.y; s0.z += u0.z; s0.w += u0.w;
        s1.x += u1.x; s1.y += u1.y; s1.z += u1.z; s1.w += u1.w;
        s2.x += u2.x; s2.y += u2.y; s2.z += u2.z; s2.w += u2.w;
        s3.x += u3.x; s3.y += u3.y; s3.z += u3.z; s3.w += u3.w;
    }
    s0.x += s1.x; s0.y += s1.y; s0.z += s1.z; s0.w += s1.w;
    s2.x += s3.x; s2.y += s3.y; s2.z += s3.z; s2.w += s3.w;
    float4 v;
    v.x = s0.x + s2.x; v.y = s0.y + s2.y; v.z = s0.z + s2.z; v.w = s0.w + s2.w;

    float4* dst = out4 + (size_t)b * (N_DIM * R_DIM / 4) + (size_t)seg * 2048;
#pragma unroll
    for (int i = 0; i < 8; ++i)
        dst[(size_t)i * 256 + t] = v;
}

// ---------------------------------------------------------------------------
extern "C" void kernel_launch(void* const* d_in, const int* in_sizes, int n_in,
                              void* d_out, int out_size) {
    const float* x  = (const float*)d_in[0];
    const float* W  = (const float*)d_in[1];
    const float* pw = (const float*)d_in[2];
    float4* out4    = (float4*)d_out;

    (void)in_sizes; (void)n_in; (void)out_size;

    dim3 g1(CHUNKS, B_DIM);                    // 2048 blocks
    k1_colsum_partial<<<g1, 128>>>(x);

    dim3 g2(NJ, B_DIM);                        // 256 blocks
    k2proj<<<g2, 128>>>(W, pw);

    k3sum_broadcast<<<1024, 256>>>(out4);      // 1024 blocks
}